// round 11
// baseline (speedup 1.0000x reference)
#include <cuda_runtime.h>
#include <cuda_bf16.h>
#include <math.h>

#define Bdim 4
#define Ldim 2048
#define Cdim 1024
#define Hdim 16
#define Mdim (Bdim*Ldim)          // 8192
#define MAX_SCALE_MUL 4.605170185988091f   // log(100)
#define BHL (Bdim*Hdim*Ldim)      // 131072

// ---- scratch (__device__ globals; allocation-free rule) ----
// packed bf16x2 hi/lo operand arrays (u32 = one bf16 pair, 512 u32 per 1024-col row)
__device__ unsigned g_xhi   [Mdim*512],  g_xlo   [Mdim*512];
__device__ unsigned g_wqkvhi[3072*512],  g_wqkvlo[3072*512];
__device__ unsigned g_wprohi[1024*512],  g_wprolo[1024*512];
__device__ unsigned g_ctxhi [Mdim*512],  g_ctxlo [Mdim*512];
__device__ unsigned g_qhi   [BHL*32],    g_qlo   [BHL*32];    // normalized q  [b,h,l][32 u32]
__device__ unsigned g_khi   [BHL*32],    g_klo   [BHL*32];    // normalized k
__device__ unsigned g_vthi  [Bdim*Hdim*64*1024], g_vtlo[Bdim*Hdim*64*1024]; // [b,h,d][1024 u32]
// fp32 intermediates
__device__ float g_q  [BHL*64];   // pre-norm q [b,h,l,d]
__device__ float g_k  [BHL*64];
__device__ float g_vt [BHL*64];   // [b,h,d,l]

// ============================================================
// helpers
// ============================================================
__device__ __forceinline__ void split2(float x0, float x1, unsigned &hi, unsigned &lo) {
    __nv_bfloat162 h2 = __floats2bfloat162_rn(x0, x1);
    float hx = __bfloat162float(h2.x), hy = __bfloat162float(h2.y);
    __nv_bfloat162 l2 = __floats2bfloat162_rn(x0 - hx, x1 - hy);
    hi = *reinterpret_cast<unsigned*>(&h2);
    lo = *reinterpret_cast<unsigned*>(&l2);
}

__device__ __forceinline__ void mma16816(float* c, const unsigned* a, const unsigned* b) {
    asm volatile(
        "mma.sync.aligned.m16n8k16.row.col.f32.bf16.bf16.f32 "
        "{%0,%1,%2,%3},{%4,%5,%6,%7},{%8,%9},{%0,%1,%2,%3};\n"
        : "+f"(c[0]), "+f"(c[1]), "+f"(c[2]), "+f"(c[3])
        : "r"(a[0]), "r"(a[1]), "r"(a[2]), "r"(a[3]), "r"(b[0]), "r"(b[1]));
}
// acc += ah*bl + al*bh + ah*bh   (drops lo*lo, ~4e-6 rel)
__device__ __forceinline__ void mma3(float* c, const unsigned* ah, const unsigned* al,
                                     const unsigned* bh, const unsigned* bl) {
    mma16816(c, ah, bl);
    mma16816(c, al, bh);
    mma16816(c, ah, bh);
}

__device__ __forceinline__ void cpa16(unsigned dst, const void* src) {
    asm volatile("cp.async.cg.shared.global [%0], [%1], 16;" :: "r"(dst), "l"(src) : "memory");
}
__device__ __forceinline__ void cpa_commit() { asm volatile("cp.async.commit_group;" ::: "memory"); }
__device__ __forceinline__ void cpa_wait0()  { asm volatile("cp.async.wait_group 0;" ::: "memory"); }
__device__ __forceinline__ void cpa_wait1()  { asm volatile("cp.async.wait_group 1;" ::: "memory"); }

// ============================================================
// elementwise fp32 -> packed bf16 hi/lo split
// ============================================================
__global__ __launch_bounds__(256) void split_ker(
    const float* __restrict__ src, unsigned* __restrict__ hi,
    unsigned* __restrict__ lo, int n4)
{
    int i = blockIdx.x * 256 + threadIdx.x;
    if (i < n4) {
        float4 v = ((const float4*)src)[i];
        unsigned h0,l0,h1,l1;
        split2(v.x, v.y, h0, l0);
        split2(v.z, v.w, h1, l1);
        ((uint2*)hi)[i] = make_uint2(h0, h1);
        ((uint2*)lo)[i] = make_uint2(l0, l1);
    }
}

// ============================================================
// GEMM: C[M,N] = A[M,1024].W[N,1024]^T  (pre-split operands)
// block tile 128(M) x 64(N), BK=64, 2-stage cp.async, 8 warps
// stage layout (bytes): Ah@0 16K | Al@16K | Wh@32K 8K | Wl@40K 8K  = 48K
// 2 stages = 96KB -> 2 CTAs/SM.
// warps: wm = wid&3 (M slice of 32), wn = wid>>2 (N slice of 32)
// MODE 0: QKV scatter epilogue; MODE 1: proj + bias -> out
// ============================================================
__device__ __forceinline__ void gemm_issue_tile(
    const unsigned* __restrict__ Ah, const unsigned* __restrict__ Al,
    const unsigned* __restrict__ Wh, const unsigned* __restrict__ Wl,
    int bm, int bn, int kt, unsigned sb, int tid)
{
    const int ku = kt * 32;
    {   // A: 128 rows x 32 u32, 2 threads/row, 4 chunks each
        const int r = tid >> 1;
        const unsigned* g0 = Ah + (size_t)(bm + r)*512 + ku;
        const unsigned* g1 = Al + (size_t)(bm + r)*512 + ku;
#pragma unroll
        for (int c = 0; c < 4; c++) {
            int cc = (tid & 1)*4 + c;
            int p  = cc ^ (r & 7);
            unsigned off = (unsigned)(r*32 + p*4) * 4u;
            cpa16(sb + off,         g0 + cc*4);
            cpa16(sb + 16384 + off, g1 + cc*4);
        }
    }
    {   // W: 64 rows x 32 u32, 4 threads/row, 2 chunks each
        const int r = tid >> 2;
        const unsigned* g2 = Wh + (size_t)(bn + r)*512 + ku;
        const unsigned* g3 = Wl + (size_t)(bn + r)*512 + ku;
#pragma unroll
        for (int c = 0; c < 2; c++) {
            int cc = (tid & 3)*2 + c;
            int p  = cc ^ (r & 7);
            unsigned off = (unsigned)(r*32 + p*4) * 4u;
            cpa16(sb + 32768 + off, g2 + cc*4);
            cpa16(sb + 40960 + off, g3 + cc*4);
        }
    }
}

template<int MODE>
__global__ __launch_bounds__(256) void gemm_ker(
    const unsigned* __restrict__ Ahg, const unsigned* __restrict__ Alg,
    const unsigned* __restrict__ Whg, const unsigned* __restrict__ Wlg,
    const float* __restrict__ bq, const float* __restrict__ bv,
    float* __restrict__ out)
{
    extern __shared__ unsigned smg[];
    const int tid  = threadIdx.x;
    const int lane = tid & 31;
    const int wid  = tid >> 5;
    const int wm   = wid & 3, wn = wid >> 2;
    const int qr   = lane >> 2, qc = lane & 3;
    const int bm = blockIdx.y * 128, bn = blockIdx.x * 64;
    const unsigned smbase = (unsigned)__cvta_generic_to_shared(smg);

    float acc[2][4][4];
#pragma unroll
    for (int i = 0; i < 2; i++)
#pragma unroll
        for (int j = 0; j < 4; j++)
#pragma unroll
            for (int t = 0; t < 4; t++) acc[i][j][t] = 0.f;

    gemm_issue_tile(Ahg, Alg, Whg, Wlg, bm, bn, 0, smbase, tid);
    cpa_commit();

    for (int kt = 0; kt < 16; kt++) {
        if (kt + 1 < 16) {
            gemm_issue_tile(Ahg, Alg, Whg, Wlg, bm, bn, kt + 1,
                            smbase + ((kt + 1) & 1) * 49152u, tid);
            cpa_commit();
            cpa_wait1();
        } else {
            cpa_wait0();
        }
        __syncthreads();

        const unsigned* Ahi = smg + (kt & 1) * 12288;
        const unsigned* Alo = Ahi + 4096;
        const unsigned* Whi = Ahi + 8192;
        const unsigned* Wlo = Ahi + 10240;
#pragma unroll
        for (int ks = 0; ks < 4; ks++) {
            const int c0 = ks*8 + qc, c1 = c0 + 4, sw = qr << 2;
            unsigned ah[2][4], al[2][4], bh[4][2], bl[4][2];
#pragma unroll
            for (int mt = 0; mt < 2; mt++) {
                int r0 = wm*32 + mt*16 + qr, r1 = r0 + 8;
                int i0 = r0*32 + (c0^sw), i1 = r1*32 + (c0^sw);
                int i2 = r0*32 + (c1^sw), i3 = r1*32 + (c1^sw);
                ah[mt][0]=Ahi[i0]; ah[mt][1]=Ahi[i1]; ah[mt][2]=Ahi[i2]; ah[mt][3]=Ahi[i3];
                al[mt][0]=Alo[i0]; al[mt][1]=Alo[i1]; al[mt][2]=Alo[i2]; al[mt][3]=Alo[i3];
            }
#pragma unroll
            for (int nt = 0; nt < 4; nt++) {
                int n0 = wn*32 + nt*8 + qr;
                bh[nt][0]=Whi[n0*32 + (c0^sw)]; bh[nt][1]=Whi[n0*32 + (c1^sw)];
                bl[nt][0]=Wlo[n0*32 + (c0^sw)]; bl[nt][1]=Wlo[n0*32 + (c1^sw)];
            }
#pragma unroll
            for (int mt = 0; mt < 2; mt++)
#pragma unroll
                for (int nt = 0; nt < 4; nt++)
                    mma3(acc[mt][nt], ah[mt], al[mt], bh[nt], bl[nt]);
        }
        __syncthreads();
    }

    if (MODE == 1) {
#pragma unroll
        for (int mt = 0; mt < 2; mt++)
#pragma unroll
            for (int nt = 0; nt < 4; nt++) {
                int m = bm + wm*32 + mt*16 + qr;
                int n = bn + wn*32 + nt*8 + qc*2;
                float b0 = bq[n], b1 = bq[n+1];
                *(float2*)(out + (size_t)m*Cdim + n)
                    = make_float2(acc[mt][nt][0] + b0, acc[mt][nt][1] + b1);
                *(float2*)(out + (size_t)(m+8)*Cdim + n)
                    = make_float2(acc[mt][nt][2] + b0, acc[mt][nt][3] + b1);
            }
    } else {
        const int which = bn >> 10;        // 0:q 1:k 2:v (64-col block in one head)
        const int cb = bn & 1023;
        const int h = cb >> 6;
#pragma unroll
        for (int mt = 0; mt < 2; mt++)
#pragma unroll
            for (int nt = 0; nt < 4; nt++) {
                int nloc = wn*32 + nt*8 + qc*2;
                int ncol = cb + nloc;
                int d = ncol & 63;
                float b0 = 0.f, b1 = 0.f;
                if (which == 0) { b0 = bq[ncol]; b1 = bq[ncol+1]; }
                if (which == 2) { b0 = bv[ncol]; b1 = bv[ncol+1]; }
#pragma unroll
                for (int hh = 0; hh < 2; hh++) {
                    int m = bm + wm*32 + mt*16 + qr + hh*8;
                    int b = m >> 11, l = m & (Ldim - 1);
                    float v0 = acc[mt][nt][hh*2]   + b0;
                    float v1 = acc[mt][nt][hh*2+1] + b1;
                    if (which == 2) {
                        size_t base = ((size_t)(b*Hdim + h)*64 + d)*Ldim + l;
                        g_vt[base]        = v0;
                        g_vt[base + Ldim] = v1;
                    } else {
                        float* dst = (which == 0) ? g_q : g_k;
                        *(float2*)(dst + ((size_t)(b*Hdim + h)*Ldim + l)*64 + d)
                            = make_float2(v0, v1);
                    }
                }
            }
    }
}

// ============================================================
// L2-normalize q,k rows; q *= exp(min(sml[h], log100));
// writes packed bf16x2 hi/lo directly.
// ============================================================
__global__ __launch_bounds__(256) void norm_kernel(const float* __restrict__ sml)
{
    const int NR = BHL;
    int w = blockIdx.x * 8 + (threadIdx.x >> 5);
    int lane = threadIdx.x & 31;
    bool is_q = (w < NR);
    const float* p = is_q ? g_q : g_k;
    int r = is_q ? w : (w - NR);
    float2 v = *(const float2*)(p + (size_t)r*64 + lane*2);
    float s = v.x*v.x + v.y*v.y;
#pragma unroll
    for (int off = 16; off > 0; off >>= 1)
        s += __shfl_xor_sync(0xffffffffu, s, off);
    float mul = 1.0f;
    if (is_q) {
        int h = (r >> 11) & (Hdim - 1);
        mul = __expf(fminf(sml[h], MAX_SCALE_MUL));
    }
    float inv = mul / fmaxf(sqrtf(s), 1e-12f);
    unsigned hi, lo;
    split2(v.x*inv, v.y*inv, hi, lo);
    unsigned* dh = is_q ? g_qhi : g_khi;
    unsigned* dl = is_q ? g_qlo : g_klo;
    dh[(size_t)r*32 + lane] = hi;
    dl[(size_t)r*32 + lane] = lo;
}

// ============================================================
// Flash attention (R6 compute) + cp.async pre-split loaders.
// Block = (b,h) x 128-query tile, 8 warps, 96KB smem -> 2 CTA/SM.
// smem u32 layout: Qhi@0 Qlo@4096 Khi@8192 Klo@12288 Vhi@16384 Vlo@20480
// ============================================================
__device__ __forceinline__ void attn_issue_tile(
    const unsigned* __restrict__ Kh, const unsigned* __restrict__ Kl,
    const unsigned* __restrict__ Vh, const unsigned* __restrict__ Vl,
    int kt, unsigned sb, int tid)
{
    {   // K: 128 rows x 32 u32
        const int r = tid >> 1;
        const unsigned* g0 = Kh + (size_t)(kt*128 + r)*32;
        const unsigned* g1 = Kl + (size_t)(kt*128 + r)*32;
#pragma unroll
        for (int c = 0; c < 4; c++) {
            int cc = (tid & 1)*4 + c;
            int p  = cc ^ (r & 7);
            unsigned off = (unsigned)(r*32 + p*4) * 4u;
            cpa16(sb + 32768 + off, g0 + cc*4);
            cpa16(sb + 49152 + off, g1 + cc*4);
        }
    }
    {   // V: 64 rows (d) x 64 u32 (128 keys)
        const int r = tid >> 2;
        const unsigned* g0 = Vh + (size_t)r*1024 + kt*64;
        const unsigned* g1 = Vl + (size_t)r*1024 + kt*64;
#pragma unroll
        for (int c = 0; c < 4; c++) {
            int cc = (tid & 3)*4 + c;
            int p  = cc ^ (r & 7);
            unsigned off = (unsigned)(r*64 + p*4) * 4u;
            cpa16(sb + 65536 + off, g0 + cc*4);
            cpa16(sb + 81920 + off, g1 + cc*4);
        }
    }
}

__global__ __launch_bounds__(256) void attn_ker()
{
    extern __shared__ unsigned sma[];
    const unsigned* Qhi = sma;
    const unsigned* Qlo = sma + 4096;
    const unsigned* Khi = sma + 8192;
    const unsigned* Klo = sma + 12288;
    const unsigned* Vhi = sma + 16384;
    const unsigned* Vlo = sma + 20480;

    const int tid = threadIdx.x, lane = tid & 31, wid = tid >> 5;
    const int qr = lane >> 2, qc = lane & 3;
    const int bh = blockIdx.y, q0 = blockIdx.x * 128;
    const unsigned* Qhg = g_qhi  + (size_t)bh * Ldim * 32;
    const unsigned* Qlg = g_qlo  + (size_t)bh * Ldim * 32;
    const unsigned* Khg = g_khi  + (size_t)bh * Ldim * 32;
    const unsigned* Klg = g_klo  + (size_t)bh * Ldim * 32;
    const unsigned* Vhg = g_vthi + (size_t)bh * 64 * 1024;
    const unsigned* Vlg = g_vtlo + (size_t)bh * 64 * 1024;
    const unsigned smbase = (unsigned)__cvta_generic_to_shared(sma);

    {   // Q resident: 128 rows x 32 u32 (hi+lo)
        const int r = tid >> 1;
        const unsigned* g0 = Qhg + (size_t)(q0 + r)*32;
        const unsigned* g1 = Qlg + (size_t)(q0 + r)*32;
#pragma unroll
        for (int c = 0; c < 4; c++) {
            int cc = (tid & 1)*4 + c;
            int p  = cc ^ (r & 7);
            unsigned off = (unsigned)(r*32 + p*4) * 4u;
            cpa16(smbase + off,         g0 + cc*4);
            cpa16(smbase + 16384 + off, g1 + cc*4);
        }
    }
    attn_issue_tile(Khg, Klg, Vhg, Vlg, 0, smbase, tid);
    cpa_commit();

    float oacc[8][4];
#pragma unroll
    for (int i = 0; i < 8; i++)
#pragma unroll
        for (int t = 0; t < 4; t++) oacc[i][t] = 0.f;
    float mrow[2] = {-1e30f, -1e30f}, lrow[2] = {0.f, 0.f};

    for (int kt = 0; kt < 16; kt++) {
        cpa_wait0();
        __syncthreads();

        // ---- S = Q . K^T  (16 rows x 128 keys per warp) ----
        float sacc[16][4];
#pragma unroll
        for (int i = 0; i < 16; i++)
#pragma unroll
            for (int t = 0; t < 4; t++) sacc[i][t] = 0.f;
#pragma unroll
        for (int ks = 0; ks < 4; ks++) {
            const int c0 = ks*8 + qc, c1 = c0 + 4, sw = qr << 2;
            int r0 = wid*16 + qr, r1 = r0 + 8;
            int i0 = r0*32 + (c0^sw), i1 = r1*32 + (c0^sw);
            int i2 = r0*32 + (c1^sw), i3 = r1*32 + (c1^sw);
            unsigned ah[4] = {Qhi[i0], Qhi[i1], Qhi[i2], Qhi[i3]};
            unsigned al[4] = {Qlo[i0], Qlo[i1], Qlo[i2], Qlo[i3]};
#pragma unroll
            for (int nt = 0; nt < 16; nt++) {
                int n0 = nt*8 + qr;
                unsigned bh2[2] = {Khi[n0*32 + (c0^sw)], Khi[n0*32 + (c1^sw)]};
                unsigned bl2[2] = {Klo[n0*32 + (c0^sw)], Klo[n0*32 + (c1^sw)]};
                mma3(sacc[nt], ah, al, bh2, bl2);
            }
        }

        // ---- online softmax (quad reduce) ----
#pragma unroll
        for (int hh = 0; hh < 2; hh++) {
            float mx = -1e30f;
#pragma unroll
            for (int nt = 0; nt < 16; nt++)
                mx = fmaxf(mx, fmaxf(sacc[nt][hh*2], sacc[nt][hh*2+1]));
            mx = fmaxf(mx, __shfl_xor_sync(0xffffffffu, mx, 1));
            mx = fmaxf(mx, __shfl_xor_sync(0xffffffffu, mx, 2));
            float mnew = fmaxf(mrow[hh], mx);
            float corr = __expf(mrow[hh] - mnew);
            float rs = 0.f;
#pragma unroll
            for (int nt = 0; nt < 16; nt++) {
                float e0 = __expf(sacc[nt][hh*2]   - mnew);
                float e1 = __expf(sacc[nt][hh*2+1] - mnew);
                sacc[nt][hh*2] = e0; sacc[nt][hh*2+1] = e1;
                rs += e0 + e1;
            }
            rs += __shfl_xor_sync(0xffffffffu, rs, 1);
            rs += __shfl_xor_sync(0xffffffffu, rs, 2);
            mrow[hh] = mnew;
            lrow[hh] = lrow[hh]*corr + rs;
#pragma unroll
            for (int nt = 0; nt < 8; nt++) {
                oacc[nt][hh*2]   *= corr;
                oacc[nt][hh*2+1] *= corr;
            }
        }

        // ---- O += P . V  (P packed from sacc regs) ----
#pragma unroll
        for (int ks = 0; ks < 8; ks++) {
            unsigned ah[4], al[4];
            split2(sacc[2*ks][0],   sacc[2*ks][1],   ah[0], al[0]);
            split2(sacc[2*ks][2],   sacc[2*ks][3],   ah[1], al[1]);
            split2(sacc[2*ks+1][0], sacc[2*ks+1][1], ah[2], al[2]);
            split2(sacc[2*ks+1][2], sacc[2*ks+1][3], ah[3], al[3]);
            const int c0 = ks*8 + qc, c1 = c0 + 4, sw = qr << 2;
#pragma unroll
            for (int nt = 0; nt < 8; nt++) {
                int n0 = nt*8 + qr;
                unsigned bh2[2] = {Vhi[n0*64 + (c0^sw)], Vhi[n0*64 + (c1^sw)]};
                unsigned bl2[2] = {Vlo[n0*64 + (c0^sw)], Vlo[n0*64 + (c1^sw)]};
                mma3(oacc[nt], ah, al, bh2, bl2);
            }
        }
        __syncthreads();   // all warps done reading K/V before refill
        if (kt + 1 < 16) {
            attn_issue_tile(Khg, Klg, Vhg, Vlg, kt + 1, smbase, tid);
            cpa_commit();
        }
    }

    // ---- epilogue: normalize rows, write pre-split ctx ----
    const int b = bh >> 4, h = bh & 15;
    const float inv0 = 1.0f / lrow[0], inv1 = 1.0f / lrow[1];
    int q = q0 + wid*16 + qr;
#pragma unroll
    for (int nt = 0; nt < 8; nt++) {
        int du = h*32 + nt*4 + qc;    // u32 col in 512-wide row
        unsigned hi, lo;
        split2(oacc[nt][0]*inv0, oacc[nt][1]*inv0, hi, lo);
        g_ctxhi[(size_t)(b*Ldim + q)*512 + du] = hi;
        g_ctxlo[(size_t)(b*Ldim + q)*512 + du] = lo;
        split2(oacc[nt][2]*inv1, oacc[nt][3]*inv1, hi, lo);
        g_ctxhi[(size_t)(b*Ldim + q + 8)*512 + du] = hi;
        g_ctxlo[(size_t)(b*Ldim + q + 8)*512 + du] = lo;
    }
}

// ============================================================
extern "C" void kernel_launch(void* const* d_in, const int* in_sizes, int n_in,
                              void* d_out, int out_size)
{
    const float* x     = (const float*)d_in[0];
    const float* Wqkv  = (const float*)d_in[1];
    const float* qb    = (const float*)d_in[2];
    const float* vb    = (const float*)d_in[3];
    const float* sml   = (const float*)d_in[4];
    const float* Wproj = (const float*)d_in[5];
    const float* bproj = (const float*)d_in[6];
    float* out = (float*)d_out;

    unsigned *xhi, *xlo, *wqh, *wql, *wph, *wpl, *vth, *vtl, *chi, *clo;
    float* vt;
    cudaGetSymbolAddress((void**)&xhi, g_xhi);    cudaGetSymbolAddress((void**)&xlo, g_xlo);
    cudaGetSymbolAddress((void**)&wqh, g_wqkvhi); cudaGetSymbolAddress((void**)&wql, g_wqkvlo);
    cudaGetSymbolAddress((void**)&wph, g_wprohi); cudaGetSymbolAddress((void**)&wpl, g_wprolo);
    cudaGetSymbolAddress((void**)&vth, g_vthi);   cudaGetSymbolAddress((void**)&vtl, g_vtlo);
    cudaGetSymbolAddress((void**)&chi, g_ctxhi);  cudaGetSymbolAddress((void**)&clo, g_ctxlo);
    cudaGetSymbolAddress((void**)&vt,  g_vt);

    const int GEMM_SMEM = 98304;   // 2 x 48KB stages -> 2 CTAs/SM
    const int ATTN_SMEM = 98304;   // 96KB -> 2 CTAs/SM
    cudaFuncSetAttribute(gemm_ker<0>, cudaFuncAttributeMaxDynamicSharedMemorySize, GEMM_SMEM);
    cudaFuncSetAttribute(gemm_ker<1>, cudaFuncAttributeMaxDynamicSharedMemorySize, GEMM_SMEM);
    cudaFuncSetAttribute(attn_ker,    cudaFuncAttributeMaxDynamicSharedMemorySize, ATTN_SMEM);

    // pre-split inputs
    split_ker<<<(Mdim*Cdim/4)/256, 256>>>(x,     xhi, xlo, Mdim*Cdim/4);
    split_ker<<<(3*Cdim*Cdim/4)/256, 256>>>(Wqkv, wqh, wql, 3*Cdim*Cdim/4);
    split_ker<<<(Cdim*Cdim/4)/256, 256>>>(Wproj, wph, wpl, Cdim*Cdim/4);

    gemm_ker<0><<<dim3(3*Cdim/64, Mdim/128), 256, GEMM_SMEM>>>(
        xhi, xlo, wqh, wql, qb, vb, nullptr);

    split_ker<<<(BHL*64/4)/256, 256>>>(vt, vth, vtl, BHL*64/4);
    norm_kernel<<<(2*BHL)/8, 256>>>(sml);

    attn_ker<<<dim3(Ldim/128, Bdim*Hdim), 256, ATTN_SMEM>>>();

    gemm_ker<1><<<dim3(Cdim/64, Mdim/128), 256, GEMM_SMEM>>>(
        chi, clo, wph, wpl, bproj, nullptr, out);
}

// round 12
// speedup vs baseline: 1.5495x; 1.5495x over previous
#include <cuda_runtime.h>
#include <cuda_bf16.h>
#include <math.h>

#define Bdim 4
#define Ldim 2048
#define Cdim 1024
#define Hdim 16
#define Mdim (Bdim*Ldim)          // 8192
#define MAX_SCALE_MUL 4.605170185988091f   // log(100)
#define BHL (Bdim*Hdim*Ldim)      // 131072

// ---- scratch (__device__ globals; allocation-free rule) ----
__device__ unsigned g_xhi   [Mdim*512],  g_xlo   [Mdim*512];
__device__ unsigned g_wqkvhi[3072*512],  g_wqkvlo[3072*512];
__device__ unsigned g_wprohi[1024*512],  g_wprolo[1024*512];
__device__ unsigned g_ctxhi [Mdim*512],  g_ctxlo [Mdim*512];
__device__ float g_q  [BHL*64];   // [b,h,l,d] fp32
__device__ float g_k  [BHL*64];
__device__ float g_vt [BHL*64];   // [b,h,d,l] fp32

// ============================================================
// helpers
// ============================================================
__device__ __forceinline__ void split2(float x0, float x1, unsigned &hi, unsigned &lo) {
    __nv_bfloat162 h2 = __floats2bfloat162_rn(x0, x1);
    float hx = __bfloat162float(h2.x), hy = __bfloat162float(h2.y);
    __nv_bfloat162 l2 = __floats2bfloat162_rn(x0 - hx, x1 - hy);
    hi = *reinterpret_cast<unsigned*>(&h2);
    lo = *reinterpret_cast<unsigned*>(&l2);
}

__device__ __forceinline__ void mma16816(float* c, const unsigned* a, const unsigned* b) {
    asm volatile(
        "mma.sync.aligned.m16n8k16.row.col.f32.bf16.bf16.f32 "
        "{%0,%1,%2,%3},{%4,%5,%6,%7},{%8,%9},{%0,%1,%2,%3};\n"
        : "+f"(c[0]), "+f"(c[1]), "+f"(c[2]), "+f"(c[3])
        : "r"(a[0]), "r"(a[1]), "r"(a[2]), "r"(a[3]), "r"(b[0]), "r"(b[1]));
}
// acc += ah*bl + al*bh + ah*bh   (drops lo*lo, ~4e-6 rel)
__device__ __forceinline__ void mma3(float* c, const unsigned* ah, const unsigned* al,
                                     const unsigned* bh, const unsigned* bl) {
    mma16816(c, ah, bl);
    mma16816(c, al, bh);
    mma16816(c, ah, bh);
}

__device__ __forceinline__ void ldsm4(unsigned &d0, unsigned &d1, unsigned &d2, unsigned &d3,
                                      unsigned addr) {
    asm volatile("ldmatrix.sync.aligned.m8n8.x4.shared.b16 {%0,%1,%2,%3}, [%4];"
        : "=r"(d0), "=r"(d1), "=r"(d2), "=r"(d3) : "r"(addr));
}

__device__ __forceinline__ void cpa16(unsigned dst, const void* src) {
    asm volatile("cp.async.cg.shared.global [%0], [%1], 16;" :: "r"(dst), "l"(src) : "memory");
}
__device__ __forceinline__ void cpa_commit() { asm volatile("cp.async.commit_group;" ::: "memory"); }
__device__ __forceinline__ void cpa_wait0()  { asm volatile("cp.async.wait_group 0;" ::: "memory"); }
__device__ __forceinline__ void cpa_wait1()  { asm volatile("cp.async.wait_group 1;" ::: "memory"); }
__device__ __forceinline__ void cpa_wait2()  { asm volatile("cp.async.wait_group 2;" ::: "memory"); }

// ============================================================
// elementwise fp32 -> packed bf16 hi/lo split
// ============================================================
__global__ __launch_bounds__(256) void split_ker(
    const float* __restrict__ src, unsigned* __restrict__ hi,
    unsigned* __restrict__ lo, int n4)
{
    int i = blockIdx.x * 256 + threadIdx.x;
    if (i < n4) {
        float4 v = ((const float4*)src)[i];
        unsigned h0,l0,h1,l1;
        split2(v.x, v.y, h0, l0);
        split2(v.z, v.w, h1, l1);
        ((uint2*)hi)[i] = make_uint2(h0, h1);
        ((uint2*)lo)[i] = make_uint2(l0, l1);
    }
}

// ============================================================
// GEMM: C[M,N] = A[M,1024].W[N,1024]^T  (pre-split operands)
// CTA 128x128, BK=64, 3-stage cp.async, 8 warps (2M x 4N).
// Stage (64KB): Ahi@0 | Alo@16K | Whi@32K | Wlo@48K
// swizzle: phys 16B-chunk = chunk ^ (row&7), rows = 128B
// ============================================================
__device__ __forceinline__ void gemm_issue_tile(
    const unsigned* __restrict__ Ah, const unsigned* __restrict__ Al,
    const unsigned* __restrict__ Wh, const unsigned* __restrict__ Wl,
    int bm, int bn, int kt, unsigned sb, int tid)
{
    const int r  = tid >> 1;
    const int ku = kt * 32;
    const unsigned* g0 = Ah + (size_t)(bm + r)*512 + ku;
    const unsigned* g1 = Al + (size_t)(bm + r)*512 + ku;
    const unsigned* g2 = Wh + (size_t)(bn + r)*512 + ku;
    const unsigned* g3 = Wl + (size_t)(bn + r)*512 + ku;
#pragma unroll
    for (int c = 0; c < 4; c++) {
        int cc = (tid & 1)*4 + c;
        int p  = cc ^ (r & 7);
        unsigned off = (unsigned)(r*32 + p*4) * 4u;
        cpa16(sb + off,         g0 + cc*4);
        cpa16(sb + 16384 + off, g1 + cc*4);
        cpa16(sb + 32768 + off, g2 + cc*4);
        cpa16(sb + 49152 + off, g3 + cc*4);
    }
}

template<int MODE>
__global__ __launch_bounds__(256) void gemm_ker(
    const unsigned* __restrict__ Ahg, const unsigned* __restrict__ Alg,
    const unsigned* __restrict__ Whg, const unsigned* __restrict__ Wlg,
    const float* __restrict__ bq, const float* __restrict__ bv,
    float* __restrict__ out)
{
    extern __shared__ unsigned smg[];
    const int tid  = threadIdx.x;
    const int lane = tid & 31;
    const int wid  = tid >> 5;
    const int wm   = wid >> 2, wn = wid & 3;
    const int qr   = lane >> 2, qc = lane & 3;
    const int j    = lane >> 3, rr = lane & 7;   // ldsm lane decomposition
    const int bm = blockIdx.y * 128, bn = blockIdx.x * 128;
    const unsigned smbase = (unsigned)__cvta_generic_to_shared(smg);

    // per-lane ldsm row offsets (bytes within a 16KB tile)
    unsigned a_off[4], b_off[2];
#pragma unroll
    for (int mt = 0; mt < 4; mt++)
        a_off[mt] = (unsigned)((wm*64 + mt*16 + ((j & 1) << 3) + rr) * 128);
#pragma unroll
    for (int p = 0; p < 2; p++)
        b_off[p] = (unsigned)((wn*32 + (2*p + (j >> 1))*8 + rr) * 128);

    float acc[4][4][4];
#pragma unroll
    for (int i = 0; i < 4; i++)
#pragma unroll
        for (int jj = 0; jj < 4; jj++)
#pragma unroll
            for (int t = 0; t < 4; t++) acc[i][jj][t] = 0.f;

#pragma unroll
    for (int s = 0; s < 3; s++) {
        gemm_issue_tile(Ahg, Alg, Whg, Wlg, bm, bn, s, smbase + s*65536u, tid);
        cpa_commit();
    }

    for (int kt = 0; kt < 16; kt++) {
        if (kt <= 13) cpa_wait2(); else if (kt == 14) cpa_wait1(); else cpa_wait0();
        __syncthreads();

        const unsigned sA = smbase + (unsigned)(kt % 3) * 65536u;
        const unsigned sW = sA + 32768u;
#pragma unroll
        for (int ks = 0; ks < 4; ks++) {
            const unsigned swA = (unsigned)((((2*ks + (j >> 1)) ^ rr)) << 4);
            const unsigned swB = (unsigned)((((2*ks + (j & 1)) ^ rr)) << 4);
            unsigned ah[4][4], al[4][4], bh[4][2], bl[4][2];
#pragma unroll
            for (int mt = 0; mt < 4; mt++) {
                ldsm4(ah[mt][0], ah[mt][1], ah[mt][2], ah[mt][3], sA + a_off[mt] + swA);
                ldsm4(al[mt][0], al[mt][1], al[mt][2], al[mt][3], sA + 16384u + a_off[mt] + swA);
            }
#pragma unroll
            for (int p = 0; p < 2; p++) {
                ldsm4(bh[2*p][0], bh[2*p][1], bh[2*p+1][0], bh[2*p+1][1], sW + b_off[p] + swB);
                ldsm4(bl[2*p][0], bl[2*p][1], bl[2*p+1][0], bl[2*p+1][1], sW + 16384u + b_off[p] + swB);
            }
#pragma unroll
            for (int mt = 0; mt < 4; mt++)
#pragma unroll
                for (int nt = 0; nt < 4; nt++)
                    mma3(acc[mt][nt], ah[mt], al[mt], bh[nt], bl[nt]);
        }
        __syncthreads();
        if (kt + 3 < 16) {
            gemm_issue_tile(Ahg, Alg, Whg, Wlg, bm, bn, kt + 3,
                            smbase + (unsigned)(kt % 3) * 65536u, tid);
            cpa_commit();
        }
    }

    if (MODE == 1) {
#pragma unroll
        for (int mt = 0; mt < 4; mt++)
#pragma unroll
            for (int nt = 0; nt < 4; nt++) {
                int m = bm + wm*64 + mt*16 + qr;
                int n = bn + wn*32 + nt*8 + qc*2;
                float b0 = bq[n], b1 = bq[n+1];
                *(float2*)(out + (size_t)m*Cdim + n)
                    = make_float2(acc[mt][nt][0] + b0, acc[mt][nt][1] + b1);
                *(float2*)(out + (size_t)(m+8)*Cdim + n)
                    = make_float2(acc[mt][nt][2] + b0, acc[mt][nt][3] + b1);
            }
    } else {
        const int which = bn >> 10;        // 0:q 1:k 2:v
        const int cb = bn & 1023;
#pragma unroll
        for (int mt = 0; mt < 4; mt++)
#pragma unroll
            for (int nt = 0; nt < 4; nt++) {
                int nloc = wn*32 + nt*8 + qc*2;
                int ncol = cb + nloc;
                int h = ncol >> 6, d = ncol & 63;
                float b0 = 0.f, b1 = 0.f;
                if (which == 0) { b0 = bq[ncol]; b1 = bq[ncol+1]; }
                if (which == 2) { b0 = bv[ncol]; b1 = bv[ncol+1]; }
#pragma unroll
                for (int hh = 0; hh < 2; hh++) {
                    int m = bm + wm*64 + mt*16 + qr + hh*8;
                    int b = m >> 11, l = m & (Ldim - 1);
                    float v0 = acc[mt][nt][hh*2]   + b0;
                    float v1 = acc[mt][nt][hh*2+1] + b1;
                    if (which == 2) {
                        size_t base = ((size_t)(b*Hdim + h)*64 + d)*Ldim + l;
                        g_vt[base]        = v0;
                        g_vt[base + Ldim] = v1;
                    } else {
                        float* dst = (which == 0) ? g_q : g_k;
                        *(float2*)(dst + ((size_t)(b*Hdim + h)*Ldim + l)*64 + d)
                            = make_float2(v0, v1);
                    }
                }
            }
    }
}

// ============================================================
// L2-normalize q,k rows (fp32 in place); q *= exp(min(sml[h],log100))
// ============================================================
__global__ __launch_bounds__(256) void norm_kernel(const float* __restrict__ sml)
{
    const int NR = BHL;
    int w = blockIdx.x * 8 + (threadIdx.x >> 5);
    int lane = threadIdx.x & 31;
    bool is_q = (w < NR);
    float* p = is_q ? g_q : g_k;
    int r = is_q ? w : (w - NR);
    float a0 = p[(size_t)r*64 + lane];
    float a1 = p[(size_t)r*64 + lane + 32];
    float s = a0*a0 + a1*a1;
#pragma unroll
    for (int off = 16; off > 0; off >>= 1)
        s += __shfl_xor_sync(0xffffffffu, s, off);
    float mul = 1.0f;
    if (is_q) {
        int h = (r >> 11) & (Hdim - 1);
        mul = __expf(fminf(sml[h], MAX_SCALE_MUL));
    }
    float inv = mul / fmaxf(sqrtf(s), 1e-12f);
    p[(size_t)r*64 + lane]      = a0 * inv;
    p[(size_t)r*64 + lane + 32] = a1 * inv;
}

// ============================================================
// attention tile loaders (fp32 -> split -> swizzled smem)
// ============================================================
__device__ __forceinline__ void load_tile_128x64_f32(
    const float* __restrict__ src, size_t row0,
    unsigned* __restrict__ Hi, unsigned* __restrict__ Lo, int tid)
{
#pragma unroll
    for (int p = 0; p < 8; p++) {
        int r = p*16 + (tid >> 4);
        int jj = tid & 15;
        const float4 v = *(const float4*)(src + (row0 + r)*64 + jj*4);
        unsigned h0,l0,h1,l1;
        split2(v.x, v.y, h0, l0);
        split2(v.z, v.w, h1, l1);
        int c = (2*jj) ^ ((r & 7) << 2);
        *(uint2*)&Hi[r*32 + c] = make_uint2(h0, h1);
        *(uint2*)&Lo[r*32 + c] = make_uint2(l0, l1);
    }
}

__device__ __forceinline__ void load_vt_tile_f32(
    const float* __restrict__ Vg, int l0,
    unsigned* __restrict__ Hi, unsigned* __restrict__ Lo, int tid)
{
#pragma unroll
    for (int p = 0; p < 8; p++) {
        int r = p*8 + (tid >> 5);
        int jj = tid & 31;
        const float4 v = *(const float4*)(Vg + (size_t)r*Ldim + l0 + jj*4);
        unsigned h0,l0_,h1,l1;
        split2(v.x, v.y, h0, l0_);
        split2(v.z, v.w, h1, l1);
        int c = (2*jj) ^ ((r & 7) << 2);
        *(uint2*)&Hi[r*64 + c] = make_uint2(h0, h1);
        *(uint2*)&Lo[r*64 + c] = make_uint2(l0_, l1);
    }
}

// ============================================================
// Flash attention (R6 structure + ldmatrix fragment reads).
// Block = (b,h) x 128-query tile, 8 warps, 96KB smem.
// smem bytes: Qhi@0 Qlo@16K Khi@32K Klo@48K Vhi@64K Vlo@80K
// ============================================================
__global__ __launch_bounds__(256) void attn_ker()
{
    extern __shared__ unsigned sma[];
    unsigned *Qhi = sma,          *Qlo = sma + 4096;
    unsigned *Khi = sma + 8192,   *Klo = sma + 12288;
    unsigned *Vhi = sma + 16384,  *Vlo = sma + 20480;

    const int tid = threadIdx.x, lane = tid & 31, wid = tid >> 5;
    const int qr = lane >> 2, qc = lane & 3;
    const int j  = lane >> 3, rr = lane & 7;
    const int bh = blockIdx.y, q0 = blockIdx.x * 128;
    const float* Qg = g_q  + (size_t)bh * Ldim * 64;
    const float* Kg = g_k  + (size_t)bh * Ldim * 64;
    const float* Vg = g_vt + (size_t)bh * 64 * Ldim;
    const unsigned smbase = (unsigned)__cvta_generic_to_shared(sma);

    load_tile_128x64_f32(Qg, q0, Qhi, Qlo, tid);

    // ldsm per-lane row offsets
    const unsigned q_off = (unsigned)((wid*16 + ((j & 1) << 3) + rr) * 128);
    unsigned k_off[8], v_off[4];
#pragma unroll
    for (int p = 0; p < 8; p++)
        k_off[p] = (unsigned)(((2*p + (j >> 1))*8 + rr) * 128);
#pragma unroll
    for (int p = 0; p < 4; p++)
        v_off[p] = (unsigned)(((2*p + (j >> 1))*8 + rr) * 256);

    float oacc[8][4];
#pragma unroll
    for (int i = 0; i < 8; i++)
#pragma unroll
        for (int t = 0; t < 4; t++) oacc[i][t] = 0.f;
    float mrow[2] = {-1e30f, -1e30f}, lrow[2] = {0.f, 0.f};

    for (int kt = 0; kt < Ldim/128; kt++) {
        __syncthreads();
        load_tile_128x64_f32(Kg, (size_t)kt*128, Khi, Klo, tid);
        load_vt_tile_f32(Vg, kt*128, Vhi, Vlo, tid);
        __syncthreads();

        // ---- S = Q . K^T ----
        float sacc[16][4];
#pragma unroll
        for (int i = 0; i < 16; i++)
#pragma unroll
            for (int t = 0; t < 4; t++) sacc[i][t] = 0.f;
#pragma unroll
        for (int ks = 0; ks < 4; ks++) {
            const unsigned swA = (unsigned)(((2*ks + (j >> 1)) ^ rr) << 4);
            const unsigned swB = (unsigned)(((2*ks + (j & 1)) ^ rr) << 4);
            unsigned ah[4], al[4];
            ldsm4(ah[0], ah[1], ah[2], ah[3], smbase + q_off + swA);
            ldsm4(al[0], al[1], al[2], al[3], smbase + 16384u + q_off + swA);
#pragma unroll
            for (int p = 0; p < 8; p++) {
                unsigned bh4[4], bl4[4];
                ldsm4(bh4[0], bh4[1], bh4[2], bh4[3], smbase + 32768u + k_off[p] + swB);
                ldsm4(bl4[0], bl4[1], bl4[2], bl4[3], smbase + 49152u + k_off[p] + swB);
                mma3(sacc[2*p],   ah, al, bh4,     bl4);
                mma3(sacc[2*p+1], ah, al, bh4 + 2, bl4 + 2);
            }
        }

        // ---- online softmax (quad reduce) ----
#pragma unroll
        for (int hh = 0; hh < 2; hh++) {
            float mx = -1e30f;
#pragma unroll
            for (int nt = 0; nt < 16; nt++)
                mx = fmaxf(mx, fmaxf(sacc[nt][hh*2], sacc[nt][hh*2+1]));
            mx = fmaxf(mx, __shfl_xor_sync(0xffffffffu, mx, 1));
            mx = fmaxf(mx, __shfl_xor_sync(0xffffffffu, mx, 2));
            float mnew = fmaxf(mrow[hh], mx);
            float corr = __expf(mrow[hh] - mnew);
            float rs = 0.f;
#pragma unroll
            for (int nt = 0; nt < 16; nt++) {
                float e0 = __expf(sacc[nt][hh*2]   - mnew);
                float e1 = __expf(sacc[nt][hh*2+1] - mnew);
                sacc[nt][hh*2] = e0; sacc[nt][hh*2+1] = e1;
                rs += e0 + e1;
            }
            rs += __shfl_xor_sync(0xffffffffu, rs, 1);
            rs += __shfl_xor_sync(0xffffffffu, rs, 2);
            mrow[hh] = mnew;
            lrow[hh] = lrow[hh]*corr + rs;
#pragma unroll
            for (int nt = 0; nt < 8; nt++) {
                oacc[nt][hh*2]   *= corr;
                oacc[nt][hh*2+1] *= corr;
            }
        }

        // ---- O += P . V  (P from sacc regs) ----
#pragma unroll
        for (int ks = 0; ks < 8; ks++) {
            unsigned ah[4], al[4];
            split2(sacc[2*ks][0],   sacc[2*ks][1],   ah[0], al[0]);
            split2(sacc[2*ks][2],   sacc[2*ks][3],   ah[1], al[1]);
            split2(sacc[2*ks+1][0], sacc[2*ks+1][1], ah[2], al[2]);
            split2(sacc[2*ks+1][2], sacc[2*ks+1][3], ah[3], al[3]);
            const unsigned swV = (unsigned)(((2*ks + (j & 1)) ^ rr) << 4);
#pragma unroll
            for (int p = 0; p < 4; p++) {
                unsigned bh4[4], bl4[4];
                ldsm4(bh4[0], bh4[1], bh4[2], bh4[3], smbase + 65536u + v_off[p] + swV);
                ldsm4(bl4[0], bl4[1], bl4[2], bl4[3], smbase + 81920u + v_off[p] + swV);
                mma3(oacc[2*p],   ah, al, bh4,     bl4);
                mma3(oacc[2*p+1], ah, al, bh4 + 2, bl4 + 2);
            }
        }
    }

    // ---- epilogue: normalize rows, write pre-split ctx ----
    const int b = bh >> 4, h = bh & 15;
    const float inv0 = 1.0f / lrow[0], inv1 = 1.0f / lrow[1];
    int q = q0 + wid*16 + qr;
#pragma unroll
    for (int nt = 0; nt < 8; nt++) {
        int du = h*32 + nt*4 + qc;    // u32 col in 512-wide row
        unsigned hi, lo;
        split2(oacc[nt][0]*inv0, oacc[nt][1]*inv0, hi, lo);
        g_ctxhi[(size_t)(b*Ldim + q)*512 + du] = hi;
        g_ctxlo[(size_t)(b*Ldim + q)*512 + du] = lo;
        split2(oacc[nt][2]*inv1, oacc[nt][3]*inv1, hi, lo);
        g_ctxhi[(size_t)(b*Ldim + q + 8)*512 + du] = hi;
        g_ctxlo[(size_t)(b*Ldim + q + 8)*512 + du] = lo;
    }
}

// ============================================================
extern "C" void kernel_launch(void* const* d_in, const int* in_sizes, int n_in,
                              void* d_out, int out_size)
{
    const float* x     = (const float*)d_in[0];
    const float* Wqkv  = (const float*)d_in[1];
    const float* qb    = (const float*)d_in[2];
    const float* vb    = (const float*)d_in[3];
    const float* sml   = (const float*)d_in[4];
    const float* Wproj = (const float*)d_in[5];
    const float* bproj = (const float*)d_in[6];
    float* out = (float*)d_out;

    unsigned *xhi, *xlo, *wqh, *wql, *wph, *wpl, *chi, *clo;
    cudaGetSymbolAddress((void**)&xhi, g_xhi);    cudaGetSymbolAddress((void**)&xlo, g_xlo);
    cudaGetSymbolAddress((void**)&wqh, g_wqkvhi); cudaGetSymbolAddress((void**)&wql, g_wqkvlo);
    cudaGetSymbolAddress((void**)&wph, g_wprohi); cudaGetSymbolAddress((void**)&wpl, g_wprolo);
    cudaGetSymbolAddress((void**)&chi, g_ctxhi);  cudaGetSymbolAddress((void**)&clo, g_ctxlo);

    const int GEMM_SMEM = 3 * 65536;   // 192KB, 3 stages
    const int ATTN_SMEM = 98304;       // 96KB
    cudaFuncSetAttribute(gemm_ker<0>, cudaFuncAttributeMaxDynamicSharedMemorySize, GEMM_SMEM);
    cudaFuncSetAttribute(gemm_ker<1>, cudaFuncAttributeMaxDynamicSharedMemorySize, GEMM_SMEM);
    cudaFuncSetAttribute(attn_ker,    cudaFuncAttributeMaxDynamicSharedMemorySize, ATTN_SMEM);

    split_ker<<<(Mdim*Cdim/4)/256, 256>>>(x,     xhi, xlo, Mdim*Cdim/4);
    split_ker<<<(3*Cdim*Cdim/4)/256, 256>>>(Wqkv, wqh, wql, 3*Cdim*Cdim/4);
    split_ker<<<(Cdim*Cdim/4)/256, 256>>>(Wproj, wph, wpl, Cdim*Cdim/4);

    gemm_ker<0><<<dim3(3*Cdim/128, Mdim/128), 256, GEMM_SMEM>>>(
        xhi, xlo, wqh, wql, qb, vb, nullptr);

    norm_kernel<<<(2*BHL)/8, 256>>>(sml);

    attn_ker<<<dim3(Ldim/128, Bdim*Hdim), 256, ATTN_SMEM>>>();

    gemm_ker<1><<<dim3(Cdim/128, Mdim/128), 256, GEMM_SMEM>>>(
        chi, clo, wph, wpl, bproj, nullptr, out);
}

// round 13
// speedup vs baseline: 1.5731x; 1.0153x over previous
#include <cuda_runtime.h>
#include <cuda_bf16.h>
#include <math.h>

#define Bdim 4
#define Ldim 2048
#define Cdim 1024
#define Hdim 16
#define Mdim (Bdim*Ldim)          // 8192
#define MAX_SCALE_MUL 4.605170185988091f   // log(100)
#define BHL (Bdim*Hdim*Ldim)      // 131072

// ---- scratch (__device__ globals; allocation-free rule) ----
__device__ unsigned g_xhi   [Mdim*512],  g_xlo   [Mdim*512];
__device__ unsigned g_wqkvhi[3072*512],  g_wqkvlo[3072*512];
__device__ unsigned g_wprohi[1024*512],  g_wprolo[1024*512];
__device__ unsigned g_ctxhi [Mdim*512],  g_ctxlo [Mdim*512];
__device__ float g_q  [BHL*64];   // [b,h,l,d] fp32
__device__ float g_k  [BHL*64];
__device__ float g_vt [BHL*64];   // [b,h,d,l] fp32

// ============================================================
// helpers
// ============================================================
__device__ __forceinline__ void split2(float x0, float x1, unsigned &hi, unsigned &lo) {
    __nv_bfloat162 h2 = __floats2bfloat162_rn(x0, x1);
    float hx = __bfloat162float(h2.x), hy = __bfloat162float(h2.y);
    __nv_bfloat162 l2 = __floats2bfloat162_rn(x0 - hx, x1 - hy);
    hi = *reinterpret_cast<unsigned*>(&h2);
    lo = *reinterpret_cast<unsigned*>(&l2);
}

__device__ __forceinline__ void mma16816(float* c, const unsigned* a, const unsigned* b) {
    asm volatile(
        "mma.sync.aligned.m16n8k16.row.col.f32.bf16.bf16.f32 "
        "{%0,%1,%2,%3},{%4,%5,%6,%7},{%8,%9},{%0,%1,%2,%3};\n"
        : "+f"(c[0]), "+f"(c[1]), "+f"(c[2]), "+f"(c[3])
        : "r"(a[0]), "r"(a[1]), "r"(a[2]), "r"(a[3]), "r"(b[0]), "r"(b[1]));
}
// acc += ah*bl + al*bh + ah*bh   (drops lo*lo, ~4e-6 rel)
__device__ __forceinline__ void mma3(float* c, const unsigned* ah, const unsigned* al,
                                     const unsigned* bh, const unsigned* bl) {
    mma16816(c, ah, bl);
    mma16816(c, al, bh);
    mma16816(c, ah, bh);
}

__device__ __forceinline__ void ldsm4(unsigned &d0, unsigned &d1, unsigned &d2, unsigned &d3,
                                      unsigned addr) {
    asm volatile("ldmatrix.sync.aligned.m8n8.x4.shared.b16 {%0,%1,%2,%3}, [%4];"
        : "=r"(d0), "=r"(d1), "=r"(d2), "=r"(d3) : "r"(addr));
}

__device__ __forceinline__ void cpa16(unsigned dst, const void* src) {
    asm volatile("cp.async.cg.shared.global [%0], [%1], 16;" :: "r"(dst), "l"(src) : "memory");
}
__device__ __forceinline__ void cpa_commit() { asm volatile("cp.async.commit_group;" ::: "memory"); }
__device__ __forceinline__ void cpa_wait0()  { asm volatile("cp.async.wait_group 0;" ::: "memory"); }
__device__ __forceinline__ void cpa_wait1()  { asm volatile("cp.async.wait_group 1;" ::: "memory"); }

// ============================================================
// elementwise fp32 -> packed bf16 hi/lo split
// ============================================================
__global__ __launch_bounds__(256) void split_ker(
    const float* __restrict__ src, unsigned* __restrict__ hi,
    unsigned* __restrict__ lo, int n4)
{
    int i = blockIdx.x * 256 + threadIdx.x;
    if (i < n4) {
        float4 v = ((const float4*)src)[i];
        unsigned h0,l0,h1,l1;
        split2(v.x, v.y, h0, l0);
        split2(v.z, v.w, h1, l1);
        ((uint2*)hi)[i] = make_uint2(h0, h1);
        ((uint2*)lo)[i] = make_uint2(l0, l1);
    }
}

// ============================================================
// GEMM: C[M,N] = A[M,1024].W[N,1024]^T  (pre-split operands)
// CTA 128x128, BK=32, 2-stage cp.async, 8 warps (2M x 4N), 2 CTA/SM.
// Stage (40KB): Ahi@0 | Alo@10240 | Whi@20480 | Wlo@30720
// Rows padded to 80B (16 data u32 + 4 pad): bank-group 5r mod 8
// distinct over any 8 consecutive rows -> ldmatrix conflict-free,
// NO xor swizzle needed.
// ============================================================
__device__ __forceinline__ void gemm_issue_tile(
    const unsigned* __restrict__ Ah, const unsigned* __restrict__ Al,
    const unsigned* __restrict__ Wh, const unsigned* __restrict__ Wl,
    int bm, int bn, int kt, unsigned sb, int tid)
{
    const int r  = tid >> 1;          // 0..127
    const int ku = kt * 16;           // u32 col offset (BK=32 fp32 = 16 u32)
    const unsigned* g0 = Ah + (size_t)(bm + r)*512 + ku;
    const unsigned* g1 = Al + (size_t)(bm + r)*512 + ku;
    const unsigned* g2 = Wh + (size_t)(bn + r)*512 + ku;
    const unsigned* g3 = Wl + (size_t)(bn + r)*512 + ku;
#pragma unroll
    for (int c = 0; c < 2; c++) {
        int cc = (tid & 1)*2 + c;     // chunk 0..3
        unsigned off = (unsigned)(r*80 + cc*16);
        cpa16(sb + off,          g0 + cc*4);
        cpa16(sb + 10240u + off, g1 + cc*4);
        cpa16(sb + 20480u + off, g2 + cc*4);
        cpa16(sb + 30720u + off, g3 + cc*4);
    }
}

template<int MODE>
__global__ __launch_bounds__(256, 2) void gemm_ker(
    const unsigned* __restrict__ Ahg, const unsigned* __restrict__ Alg,
    const unsigned* __restrict__ Whg, const unsigned* __restrict__ Wlg,
    const float* __restrict__ bq, const float* __restrict__ bv,
    float* __restrict__ out)
{
    extern __shared__ unsigned smg[];
    const int tid  = threadIdx.x;
    const int lane = tid & 31;
    const int wid  = tid >> 5;
    const int wm   = wid >> 2, wn = wid & 3;
    const int qr   = lane >> 2, qc = lane & 3;
    const int j    = lane >> 3, rr = lane & 7;   // ldsm lane decomposition
    const int bm = blockIdx.y * 128, bn = blockIdx.x * 128;
    const unsigned smbase = (unsigned)__cvta_generic_to_shared(smg);

    // ldsm per-lane byte offsets within a 10240B operand-half
    // A: row = base + ((j&1)<<3)+rr, chunk = (j>>1) + 2ks
    // B: row = base + ((j>>1)<<3)+rr, chunk = (j&1) + 2ks
    unsigned a_off[4], b_off[2];
#pragma unroll
    for (int mt = 0; mt < 4; mt++)
        a_off[mt] = (unsigned)((wm*64 + mt*16 + ((j & 1) << 3) + rr) * 80 + (j >> 1)*16);
#pragma unroll
    for (int p = 0; p < 2; p++)
        b_off[p] = (unsigned)((wn*32 + p*16 + ((j >> 1) << 3) + rr) * 80 + (j & 1)*16);

    float acc[4][4][4];
#pragma unroll
    for (int i = 0; i < 4; i++)
#pragma unroll
        for (int jj = 0; jj < 4; jj++)
#pragma unroll
            for (int t = 0; t < 4; t++) acc[i][jj][t] = 0.f;

    gemm_issue_tile(Ahg, Alg, Whg, Wlg, bm, bn, 0, smbase, tid);
    cpa_commit();

    for (int kt = 0; kt < 32; kt++) {
        if (kt + 1 < 32) {
            gemm_issue_tile(Ahg, Alg, Whg, Wlg, bm, bn, kt + 1,
                            smbase + ((kt + 1) & 1) * 40960u, tid);
            cpa_commit();
            cpa_wait1();
        } else {
            cpa_wait0();
        }
        __syncthreads();

        const unsigned sA = smbase + (unsigned)(kt & 1) * 40960u;
        const unsigned sW = sA + 20480u;
#pragma unroll
        for (int ks = 0; ks < 2; ks++) {
            const unsigned ko = (unsigned)(ks * 32);   // 2 chunks per k16
            unsigned ah[4][4], al[4][4], bh[4][2], bl[4][2];
#pragma unroll
            for (int mt = 0; mt < 4; mt++) {
                ldsm4(ah[mt][0], ah[mt][1], ah[mt][2], ah[mt][3], sA + a_off[mt] + ko);
                ldsm4(al[mt][0], al[mt][1], al[mt][2], al[mt][3], sA + 10240u + a_off[mt] + ko);
            }
#pragma unroll
            for (int p = 0; p < 2; p++) {
                ldsm4(bh[2*p][0], bh[2*p][1], bh[2*p+1][0], bh[2*p+1][1], sW + b_off[p] + ko);
                ldsm4(bl[2*p][0], bl[2*p][1], bl[2*p+1][0], bl[2*p+1][1], sW + 10240u + b_off[p] + ko);
            }
#pragma unroll
            for (int mt = 0; mt < 4; mt++)
#pragma unroll
                for (int nt = 0; nt < 4; nt++)
                    mma3(acc[mt][nt], ah[mt], al[mt], bh[nt], bl[nt]);
        }
        __syncthreads();
    }

    if (MODE == 1) {
#pragma unroll
        for (int mt = 0; mt < 4; mt++)
#pragma unroll
            for (int nt = 0; nt < 4; nt++) {
                int m = bm + wm*64 + mt*16 + qr;
                int n = bn + wn*32 + nt*8 + qc*2;
                float b0 = bq[n], b1 = bq[n+1];
                *(float2*)(out + (size_t)m*Cdim + n)
                    = make_float2(acc[mt][nt][0] + b0, acc[mt][nt][1] + b1);
                *(float2*)(out + (size_t)(m+8)*Cdim + n)
                    = make_float2(acc[mt][nt][2] + b0, acc[mt][nt][3] + b1);
            }
    } else {
        const int which = bn >> 10;        // 0:q 1:k 2:v
        const int cb = bn & 1023;
#pragma unroll
        for (int mt = 0; mt < 4; mt++)
#pragma unroll
            for (int nt = 0; nt < 4; nt++) {
                int nloc = wn*32 + nt*8 + qc*2;
                int ncol = cb + nloc;
                int h = ncol >> 6, d = ncol & 63;
                float b0 = 0.f, b1 = 0.f;
                if (which == 0) { b0 = bq[ncol]; b1 = bq[ncol+1]; }
                if (which == 2) { b0 = bv[ncol]; b1 = bv[ncol+1]; }
#pragma unroll
                for (int hh = 0; hh < 2; hh++) {
                    int m = bm + wm*64 + mt*16 + qr + hh*8;
                    int b = m >> 11, l = m & (Ldim - 1);
                    float v0 = acc[mt][nt][hh*2]   + b0;
                    float v1 = acc[mt][nt][hh*2+1] + b1;
                    if (which == 2) {
                        size_t base = ((size_t)(b*Hdim + h)*64 + d)*Ldim + l;
                        g_vt[base]        = v0;
                        g_vt[base + Ldim] = v1;
                    } else {
                        float* dst = (which == 0) ? g_q : g_k;
                        *(float2*)(dst + ((size_t)(b*Hdim + h)*Ldim + l)*64 + d)
                            = make_float2(v0, v1);
                    }
                }
            }
    }
}

// ============================================================
// L2-normalize q,k rows (fp32 in place); q *= exp(min(sml[h],log100))
// ============================================================
__global__ __launch_bounds__(256) void norm_kernel(const float* __restrict__ sml)
{
    const int NR = BHL;
    int w = blockIdx.x * 8 + (threadIdx.x >> 5);
    int lane = threadIdx.x & 31;
    bool is_q = (w < NR);
    float* p = is_q ? g_q : g_k;
    int r = is_q ? w : (w - NR);
    float a0 = p[(size_t)r*64 + lane];
    float a1 = p[(size_t)r*64 + lane + 32];
    float s = a0*a0 + a1*a1;
#pragma unroll
    for (int off = 16; off > 0; off >>= 1)
        s += __shfl_xor_sync(0xffffffffu, s, off);
    float mul = 1.0f;
    if (is_q) {
        int h = (r >> 11) & (Hdim - 1);
        mul = __expf(fminf(sml[h], MAX_SCALE_MUL));
    }
    float inv = mul / fmaxf(sqrtf(s), 1e-12f);
    p[(size_t)r*64 + lane]      = a0 * inv;
    p[(size_t)r*64 + lane + 32] = a1 * inv;
}

// ============================================================
// Flash attention — R6 known-good body (fp32 loaders, inline split,
// LDS.32 fragment reads); epilogue writes PRE-SPLIT ctx.
// Block = (b,h) x 128-query tile, 8 warps, 96KB smem.
// smem u32: Qhi@0 Qlo@4096 Khi@8192 Klo@12288 Vhi@16384 Vlo@20480
// ============================================================
__device__ __forceinline__ void load_tile_128x64_f32(
    const float* __restrict__ src, size_t row0,
    unsigned* __restrict__ Hi, unsigned* __restrict__ Lo, int tid)
{
#pragma unroll
    for (int p = 0; p < 8; p++) {
        int r = p*16 + (tid >> 4);
        int jj = tid & 15;
        const float4 v = *(const float4*)(src + (row0 + r)*64 + jj*4);
        unsigned h0,l0,h1,l1;
        split2(v.x, v.y, h0, l0);
        split2(v.z, v.w, h1, l1);
        int c = (2*jj) ^ ((r & 7) << 2);
        *(uint2*)&Hi[r*32 + c] = make_uint2(h0, h1);
        *(uint2*)&Lo[r*32 + c] = make_uint2(l0, l1);
    }
}

__device__ __forceinline__ void load_vt_tile_f32(
    const float* __restrict__ Vg, int l0,
    unsigned* __restrict__ Hi, unsigned* __restrict__ Lo, int tid)
{
#pragma unroll
    for (int p = 0; p < 8; p++) {
        int r = p*8 + (tid >> 5);
        int jj = tid & 31;
        const float4 v = *(const float4*)(Vg + (size_t)r*Ldim + l0 + jj*4);
        unsigned h0,l0_,h1,l1;
        split2(v.x, v.y, h0, l0_);
        split2(v.z, v.w, h1, l1);
        int c = (2*jj) ^ ((r & 7) << 2);
        *(uint2*)&Hi[r*64 + c] = make_uint2(h0, h1);
        *(uint2*)&Lo[r*64 + c] = make_uint2(l0_, l1);
    }
}

__global__ __launch_bounds__(256) void attn_ker()
{
    extern __shared__ unsigned sma[];
    unsigned *Qhi = sma,          *Qlo = sma + 4096;
    unsigned *Khi = sma + 8192,   *Klo = sma + 12288;
    unsigned *Vhi = sma + 16384,  *Vlo = sma + 20480;

    const int tid = threadIdx.x, lane = tid & 31, wid = tid >> 5;
    const int qr = lane >> 2, qc = lane & 3;
    const int bh = blockIdx.y, q0 = blockIdx.x * 128;
    const float* Qg = g_q  + (size_t)bh * Ldim * 64;
    const float* Kg = g_k  + (size_t)bh * Ldim * 64;
    const float* Vg = g_vt + (size_t)bh * 64 * Ldim;

    load_tile_128x64_f32(Qg, q0, Qhi, Qlo, tid);

    float oacc[8][4];
#pragma unroll
    for (int i = 0; i < 8; i++)
#pragma unroll
        for (int t = 0; t < 4; t++) oacc[i][t] = 0.f;
    float mrow[2] = {-1e30f, -1e30f}, lrow[2] = {0.f, 0.f};

    for (int kt = 0; kt < Ldim/128; kt++) {
        __syncthreads();
        load_tile_128x64_f32(Kg, (size_t)kt*128, Khi, Klo, tid);
        load_vt_tile_f32(Vg, kt*128, Vhi, Vlo, tid);
        __syncthreads();

        // ---- S = Q . K^T  (16 q rows x 128 keys per warp) ----
        float sacc[16][4];
#pragma unroll
        for (int i = 0; i < 16; i++)
#pragma unroll
            for (int t = 0; t < 4; t++) sacc[i][t] = 0.f;
#pragma unroll
        for (int ks = 0; ks < 4; ks++) {
            const int c0 = ks*8 + qc, c1 = c0 + 4, sw = qr << 2;
            int r0 = wid*16 + qr, r1 = r0 + 8;
            int i0 = r0*32 + (c0^sw), i1 = r1*32 + (c0^sw);
            int i2 = r0*32 + (c1^sw), i3 = r1*32 + (c1^sw);
            unsigned ah[4] = {Qhi[i0], Qhi[i1], Qhi[i2], Qhi[i3]};
            unsigned al[4] = {Qlo[i0], Qlo[i1], Qlo[i2], Qlo[i3]};
#pragma unroll
            for (int nt = 0; nt < 16; nt++) {
                int n0 = nt*8 + qr;
                unsigned bh2[2] = {Khi[n0*32 + (c0^sw)], Khi[n0*32 + (c1^sw)]};
                unsigned bl2[2] = {Klo[n0*32 + (c0^sw)], Klo[n0*32 + (c1^sw)]};
                mma3(sacc[nt], ah, al, bh2, bl2);
            }
        }

        // ---- online softmax (quad reduce) ----
#pragma unroll
        for (int hh = 0; hh < 2; hh++) {
            float mx = -1e30f;
#pragma unroll
            for (int nt = 0; nt < 16; nt++)
                mx = fmaxf(mx, fmaxf(sacc[nt][hh*2], sacc[nt][hh*2+1]));
            mx = fmaxf(mx, __shfl_xor_sync(0xffffffffu, mx, 1));
            mx = fmaxf(mx, __shfl_xor_sync(0xffffffffu, mx, 2));
            float mnew = fmaxf(mrow[hh], mx);
            float corr = __expf(mrow[hh] - mnew);
            float rs = 0.f;
#pragma unroll
            for (int nt = 0; nt < 16; nt++) {
                float e0 = __expf(sacc[nt][hh*2]   - mnew);
                float e1 = __expf(sacc[nt][hh*2+1] - mnew);
                sacc[nt][hh*2] = e0; sacc[nt][hh*2+1] = e1;
                rs += e0 + e1;
            }
            rs += __shfl_xor_sync(0xffffffffu, rs, 1);
            rs += __shfl_xor_sync(0xffffffffu, rs, 2);
            mrow[hh] = mnew;
            lrow[hh] = lrow[hh]*corr + rs;
#pragma unroll
            for (int nt = 0; nt < 8; nt++) {
                oacc[nt][hh*2]   *= corr;
                oacc[nt][hh*2+1] *= corr;
            }
        }

        // ---- O += P . V  (P packed from sacc regs) ----
#pragma unroll
        for (int ks = 0; ks < 8; ks++) {
            unsigned ah[4], al[4];
            split2(sacc[2*ks][0],   sacc[2*ks][1],   ah[0], al[0]);
            split2(sacc[2*ks][2],   sacc[2*ks][3],   ah[1], al[1]);
            split2(sacc[2*ks+1][0], sacc[2*ks+1][1], ah[2], al[2]);
            split2(sacc[2*ks+1][2], sacc[2*ks+1][3], ah[3], al[3]);
            const int c0 = ks*8 + qc, c1 = c0 + 4, sw = qr << 2;
#pragma unroll
            for (int nt = 0; nt < 8; nt++) {
                int n0 = nt*8 + qr;
                unsigned bh2[2] = {Vhi[n0*64 + (c0^sw)], Vhi[n0*64 + (c1^sw)]};
                unsigned bl2[2] = {Vlo[n0*64 + (c0^sw)], Vlo[n0*64 + (c1^sw)]};
                mma3(oacc[nt], ah, al, bh2, bl2);
            }
        }
    }

    // ---- epilogue: normalize rows, write pre-split ctx ----
    const int b = bh >> 4, h = bh & 15;
    const float inv0 = 1.0f / lrow[0], inv1 = 1.0f / lrow[1];
    int q = q0 + wid*16 + qr;
#pragma unroll
    for (int nt = 0; nt < 8; nt++) {
        int du = h*32 + nt*4 + qc;    // u32 col in 512-wide row
        unsigned hi, lo;
        split2(oacc[nt][0]*inv0, oacc[nt][1]*inv0, hi, lo);
        g_ctxhi[(size_t)(b*Ldim + q)*512 + du] = hi;
        g_ctxlo[(size_t)(b*Ldim + q)*512 + du] = lo;
        split2(oacc[nt][2]*inv1, oacc[nt][3]*inv1, hi, lo);
        g_ctxhi[(size_t)(b*Ldim + q + 8)*512 + du] = hi;
        g_ctxlo[(size_t)(b*Ldim + q + 8)*512 + du] = lo;
    }
}

// ============================================================
extern "C" void kernel_launch(void* const* d_in, const int* in_sizes, int n_in,
                              void* d_out, int out_size)
{
    const float* x     = (const float*)d_in[0];
    const float* Wqkv  = (const float*)d_in[1];
    const float* qb    = (const float*)d_in[2];
    const float* vb    = (const float*)d_in[3];
    const float* sml   = (const float*)d_in[4];
    const float* Wproj = (const float*)d_in[5];
    const float* bproj = (const float*)d_in[6];
    float* out = (float*)d_out;

    unsigned *xhi, *xlo, *wqh, *wql, *wph, *wpl, *chi, *clo;
    cudaGetSymbolAddress((void**)&xhi, g_xhi);    cudaGetSymbolAddress((void**)&xlo, g_xlo);
    cudaGetSymbolAddress((void**)&wqh, g_wqkvhi); cudaGetSymbolAddress((void**)&wql, g_wqkvlo);
    cudaGetSymbolAddress((void**)&wph, g_wprohi); cudaGetSymbolAddress((void**)&wpl, g_wprolo);
    cudaGetSymbolAddress((void**)&chi, g_ctxhi);  cudaGetSymbolAddress((void**)&clo, g_ctxlo);

    const int GEMM_SMEM = 81920;   // 2 x 40KB stages -> 2 CTA/SM
    const int ATTN_SMEM = 98304;   // 96KB
    cudaFuncSetAttribute(gemm_ker<0>, cudaFuncAttributeMaxDynamicSharedMemorySize, GEMM_SMEM);
    cudaFuncSetAttribute(gemm_ker<1>, cudaFuncAttributeMaxDynamicSharedMemorySize, GEMM_SMEM);
    cudaFuncSetAttribute(attn_ker,    cudaFuncAttributeMaxDynamicSharedMemorySize, ATTN_SMEM);

    split_ker<<<(Mdim*Cdim/4)/256, 256>>>(x,     xhi, xlo, Mdim*Cdim/4);
    split_ker<<<(3*Cdim*Cdim/4)/256, 256>>>(Wqkv, wqh, wql, 3*Cdim*Cdim/4);
    split_ker<<<(Cdim*Cdim/4)/256, 256>>>(Wproj, wph, wpl, Cdim*Cdim/4);

    gemm_ker<0><<<dim3(3*Cdim/128, Mdim/128), 256, GEMM_SMEM>>>(
        xhi, xlo, wqh, wql, qb, vb, nullptr);

    norm_kernel<<<(2*BHL)/8, 256>>>(sml);

    attn_ker<<<dim3(Ldim/128, Bdim*Hdim), 256, ATTN_SMEM>>>();

    gemm_ker<1><<<dim3(Cdim/128, Mdim/128), 256, GEMM_SMEM>>>(
        chi, clo, wph, wpl, bproj, nullptr, out);
}